// round 2
// baseline (speedup 1.0000x reference)
#include <cuda_runtime.h>

// Scratch for pooled means [8 batches x 128 channels]
__device__ float g_pooled[1024];

// Kernel 1: pooled[b,c] = (1/65536) * sum_{h even, w even} b[b,c,h,w]
// One block per (b,c) plane (1024 blocks). Each plane is 256x256 f32.
// We read the 128 even rows fully via float4 (DRAM sectors force it anyway)
// and accumulate the .x and .z lanes (w % 4 == 0 and w % 4 == 2 — the even w).
__global__ __launch_bounds__(256, 8) void pool_kernel(const float* __restrict__ bsrc) {
    const int blk = blockIdx.x;                    // 0..1023 = b*128 + c
    const float4* __restrict__ base =
        reinterpret_cast<const float4*>(bsrc) + (size_t)blk * (65536 / 4);

    const int tid = threadIdx.x;
    float sum = 0.0f;
    // 128 even rows x 64 float4 per row = 8192 float4 per block; 32 per thread.
    #pragma unroll 8
    for (int i = tid; i < 128 * 64; i += 256) {
        const int r  = i >> 6;        // even-row index 0..127  (h = 2*r)
        const int c4 = i & 63;        // float4 index within row
        float4 v = __ldg(&base[(size_t)(2 * r) * 64 + c4]);
        sum += v.x + v.z;
    }

    // Warp reduce
    #pragma unroll
    for (int off = 16; off > 0; off >>= 1)
        sum += __shfl_xor_sync(0xFFFFFFFFu, sum, off);

    __shared__ float warp_sums[8];
    if ((tid & 31) == 0) warp_sums[tid >> 5] = sum;
    __syncthreads();

    if (tid < 8) {
        float s = warp_sums[tid];
        #pragma unroll
        for (int off = 4; off > 0; off >>= 1)
            s += __shfl_xor_sync(0xFFu, s, off);
        if (tid == 0) g_pooled[blk] = s * (1.0f / 65536.0f);
    }
}

// Kernel 2: hidden = relu(pooled @ fc1_w^T) [8,32]; out = hidden @ fc2_w^T [8,128]
// Single block, 1024 threads. All operands tiny (fit in L1/smem).
__global__ __launch_bounds__(1024, 1) void fc_kernel(const float* __restrict__ fc1_w,
                                                     const float* __restrict__ fc2_w,
                                                     float* __restrict__ out) {
    __shared__ float sp[1024];   // pooled [8][128]
    __shared__ float sh[256];    // hidden [8][32]

    const int tid = threadIdx.x;
    sp[tid] = g_pooled[tid];
    __syncthreads();

    if (tid < 256) {
        const int bb = tid >> 5;          // batch
        const int j  = tid & 31;          // hidden unit
        const float* __restrict__ w = fc1_w + j * 128;   // fc1_w [32,128]
        const float* __restrict__ p = sp + bb * 128;
        float s = 0.0f;
        #pragma unroll
        for (int c = 0; c < 128; ++c) s = fmaf(p[c], __ldg(&w[c]), s);
        sh[tid] = fmaxf(s, 0.0f);
    }
    __syncthreads();

    const int bb = tid >> 7;              // batch
    const int c  = tid & 127;             // output channel
    const float* __restrict__ w2 = fc2_w + c * 32;       // fc2_w [128,32]
    const float* __restrict__ h  = sh + bb * 32;
    float s = 0.0f;
    #pragma unroll
    for (int j = 0; j < 32; ++j) s = fmaf(h[j], __ldg(&w2[j]), s);
    out[tid] = s;
}

extern "C" void kernel_launch(void* const* d_in, const int* in_sizes, int n_in,
                              void* d_out, int out_size) {
    // metadata order: a, b, attn_w, attn_b, fc1_w, fc2_w
    const float* bsrc  = (const float*)d_in[1];
    const float* fc1_w = (const float*)d_in[4];
    const float* fc2_w = (const float*)d_in[5];
    float* out = (float*)d_out;   // [8,128,1,1] = 1024 floats

    pool_kernel<<<1024, 256>>>(bsrc);
    fc_kernel<<<1, 1024>>>(fc1_w, fc2_w, out);
}

// round 3
// speedup vs baseline: 1.6684x; 1.6684x over previous
#include <cuda_runtime.h>

// Scratch: pooled means [8 batches x 128 channels] + completion counter
__device__ float g_pooled[1024];
__device__ unsigned int g_counter = 0;

// Fused kernel:
//  Phase A (all 1024 blocks): pooled[b,c] = (1/65536) * sum_{h even, w even} b[b,c,h,w]
//    One block per (b,c) plane; read the 128 even rows via float4, sum .x+.z.
//  Phase B (last-arriving block only): hidden = relu(pooled @ fc1_w^T); out = hidden @ fc2_w^T
__global__ __launch_bounds__(256, 8) void fused_kernel(const float* __restrict__ bsrc,
                                                       const float* __restrict__ fc1_w,
                                                       const float* __restrict__ fc2_w,
                                                       float* __restrict__ out) {
    const int blk = blockIdx.x;                    // 0..1023 = b*128 + c
    const int tid = threadIdx.x;

    // ---------- Phase A: strided pooled sum over even rows ----------
    const float4* __restrict__ base =
        reinterpret_cast<const float4*>(bsrc) + (size_t)blk * (65536 / 4);

    float sum = 0.0f;
    // 128 even rows x 64 float4 per row = 8192 float4 per block; 32 per thread.
    #pragma unroll 8
    for (int i = tid; i < 128 * 64; i += 256) {
        const int r  = i >> 6;        // even-row index 0..127  (h = 2*r)
        const int c4 = i & 63;        // float4 index within row
        float4 v = __ldg(&base[(size_t)(2 * r) * 64 + c4]);
        sum += v.x + v.z;
    }

    #pragma unroll
    for (int off = 16; off > 0; off >>= 1)
        sum += __shfl_xor_sync(0xFFFFFFFFu, sum, off);

    __shared__ float warp_sums[8];
    __shared__ int is_last;
    if ((tid & 31) == 0) warp_sums[tid >> 5] = sum;
    if (tid == 0) is_last = 0;
    __syncthreads();

    if (tid == 0) {
        float s = warp_sums[0];
        #pragma unroll
        for (int w = 1; w < 8; ++w) s += warp_sums[w];
        g_pooled[blk] = s * (1.0f / 65536.0f);
        __threadfence();                              // publish before counting
        unsigned int old = atomicAdd(&g_counter, 1u);
        if (old == 1023u) {
            g_counter = 0u;                           // reset for next graph replay
            is_last = 1;
        }
    }
    __syncthreads();
    if (!is_last) return;

    // ---------- Phase B: tiny MLP (only the last block runs this) ----------
    __shared__ __align__(16) float sp[1024];          // pooled [8][128]
    __shared__ __align__(16) float sh[256];           // hidden [8][32]

    // Stage pooled (L2-hot; bypass L1 to be safe against staleness)
    #pragma unroll
    for (int k = 0; k < 4; ++k) {
        const int i = tid + k * 256;
        sp[i] = __ldcg(&g_pooled[i]);
    }
    __syncthreads();

    // hidden[b][j] = relu( sum_c pooled[b][c] * fc1_w[j][c] )
    {
        const int j  = tid & 31;                      // hidden unit 0..31
        const int bb = tid >> 5;                      // batch 0..7
        const float4* __restrict__ w4 = reinterpret_cast<const float4*>(fc1_w) + j * 32;
        const float4* __restrict__ p4 = reinterpret_cast<const float4*>(sp) + bb * 32;
        float s = 0.0f;
        #pragma unroll
        for (int k = 0; k < 32; ++k) {
            float4 w = __ldg(&w4[k]);
            float4 p = p4[k];
            s = fmaf(w.x, p.x, s);
            s = fmaf(w.y, p.y, s);
            s = fmaf(w.z, p.z, s);
            s = fmaf(w.w, p.w, s);
        }
        sh[tid] = fmaxf(s, 0.0f);                     // sh[b*32+j]
    }
    __syncthreads();

    // out[b][c] = sum_j hidden[b][j] * fc2_w[c][j]   (4 outputs per thread)
    #pragma unroll
    for (int k = 0; k < 4; ++k) {
        const int idx = tid + k * 256;                // 0..1023 = b*128 + c
        const int bb  = idx >> 7;
        const int c   = idx & 127;
        const float4* __restrict__ w4 = reinterpret_cast<const float4*>(fc2_w) + c * 8;
        const float4* __restrict__ h4 = reinterpret_cast<const float4*>(sh) + bb * 8;
        float s = 0.0f;
        #pragma unroll
        for (int q = 0; q < 8; ++q) {
            float4 w = __ldg(&w4[q]);
            float4 h = h4[q];
            s = fmaf(w.x, h.x, s);
            s = fmaf(w.y, h.y, s);
            s = fmaf(w.z, h.z, s);
            s = fmaf(w.w, h.w, s);
        }
        out[idx] = s;
    }
}

extern "C" void kernel_launch(void* const* d_in, const int* in_sizes, int n_in,
                              void* d_out, int out_size) {
    // metadata order: a, b, attn_w, attn_b, fc1_w, fc2_w
    const float* bsrc  = (const float*)d_in[1];
    const float* fc1_w = (const float*)d_in[4];
    const float* fc2_w = (const float*)d_in[5];
    float* out = (float*)d_out;   // [8,128,1,1] = 1024 floats

    fused_kernel<<<1024, 256>>>(bsrc, fc1_w, fc2_w, out);
}